// round 14
// baseline (speedup 1.0000x reference)
#include <cuda_runtime.h>
#include <cuda_bf16.h>

// CBOW_60593398612478 — GB300 sm_103a
//
// out[b, c, :] = sum_l emb[tok(b,l,c)], tok = x[b, l+off_c] (OOB -> token 0),
// offsets order c: [-1, -2, +1, +2].
//
// Algebraic identity: with S_b = sum_{l=0}^{L-1} emb[x[b,l]],
//   c=-1: S - emb[x[L-1]]               + 1*emb[0]
//   c=-2: S - emb[x[L-1]] - emb[x[L-2]] + 2*emb[0]
//   c=+1: S - emb[x[0]]                 + 1*emb[0]
//   c=+2: S - emb[x[0]]  - emb[x[1]]    + 2*emb[0]
// -> ONE gather pass over B*L rows instead of four (4x traffic reduction).
//
// R9 -> R10: fused the 6.1us final_kernel (grid=64, occ 6.6%, pure latency)
// into the accum kernel via threadfence-reduction: last CTA per batch does
// the reduce + corrections. Counter self-resets -> graph-replay safe.

#define BB     64
#define LL     2048
#define EE     128
#define EE4    (EE / 4)        // 32 float4 per embedding row
#define NSPLIT 32
#define CHUNK  (LL / NSPLIT)   // 64 tokens per CTA
#define TPW    (CHUNK / 4)     // 16 tokens per warp

// Partial sums scratch: [B][NSPLIT][E] floats = 1 MB, as float4.
__device__ float4 g_part[BB * NSPLIT * EE4];
// Per-batch arrival counters (zero-init; last arriver resets to 0 -> replay-safe).
__device__ unsigned int g_cnt[BB];

// ---------------------------------------------------------------------------
// Inline dtype sniff: x is declared int64 in the reference, but may arrive as
// int32 (jax demotes int64 silently unless x64 is enabled). Tokens < 1e5 <
// 2^31, so for little-endian int64 every odd 32-bit word is 0. Sample 16 odd
// words of the first 32 words; all-zero -> stride 2 (int64 low words).
// Same input words for every CTA -> same result -> deterministic.
// ---------------------------------------------------------------------------
__device__ __forceinline__ int sniff_stride(const int* __restrict__ xi) {
    int odd = 0;
#pragma unroll
    for (int i = 1; i < 32; i += 2) odd |= __ldg(&xi[i]);
    return (odd == 0) ? 2 : 1;
}

// ---------------------------------------------------------------------------
// Fused kernel: grid (B, NSPLIT), block 128 = 4 warps.
// Phase 1 (all CTAs): warp w sums TPW=16 token rows; lane owns the float4 at
//   dims [4*lane..4*lane+3] (one warp LDG.E.128 covers a full 512 B row).
//   Fully unrolled -> up to 16 independent LDG.128 in flight per thread.
// Phase 2 (last CTA per batch): reduce the NSPLIT partials (all L2-hot),
//   apply the 5 edge-gather corrections, write [B, 4, E].
// ---------------------------------------------------------------------------
__global__ __launch_bounds__(128) void cbow_fused_kernel(
    const int* __restrict__ xi, const float* __restrict__ emb,
    float* __restrict__ out
) {
    const int b    = blockIdx.x;
    const int s    = blockIdx.y;
    const int tid  = threadIdx.x;
    const int w    = tid >> 5;
    const int lane = tid & 31;
    const int stride = sniff_stride(xi);

    // ---- Phase 1: partial gather-sum ----
    __shared__ int toks[CHUNK];
    const int base = b * LL + s * CHUNK;
    if (tid < CHUNK) toks[tid] = xi[(base + tid) * stride];
    __syncthreads();

    const float4* __restrict__ emb4 = (const float4*)emb;
    float4 acc = make_float4(0.f, 0.f, 0.f, 0.f);
#pragma unroll
    for (int i = 0; i < TPW; i++) {
        const int t = toks[w * TPW + i];
        const float4 v = __ldg(&emb4[t * EE4 + lane]);
        acc.x += v.x; acc.y += v.y; acc.z += v.z; acc.w += v.w;
    }

    __shared__ float4 red[4][EE4];
    red[w][lane] = acc;
    __syncthreads();

    if (tid < EE4) {
        float4 a = red[0][tid];
        const float4 r1 = red[1][tid];
        const float4 r2 = red[2][tid];
        const float4 r3 = red[3][tid];
        a.x += r1.x + r2.x + r3.x;
        a.y += r1.y + r2.y + r3.y;
        a.z += r1.z + r2.z + r3.z;
        a.w += r1.w + r2.w + r3.w;
        g_part[(b * NSPLIT + s) * EE4 + tid] = a;
    }

    // ---- Arrival protocol (threadfence reduction pattern) ----
    __threadfence();  // release: partial visible before counter bump
    __shared__ int is_last;
    if (tid == 0) {
        const unsigned int old = atomicAdd(&g_cnt[b], 1u);
        is_last = (old == NSPLIT - 1);
        if (is_last) g_cnt[b] = 0;  // reset for next graph replay
    }
    __syncthreads();
    if (!is_last) return;
    __threadfence();  // acquire side

    // ---- Phase 2: final reduce + edge corrections (one CTA per batch) ----
    const int d = tid;  // 0..127, one thread per embedding dim
    const float* __restrict__ part = (const float*)g_part;
    float S = 0.0f;
#pragma unroll
    for (int ss = 0; ss < NSPLIT; ss++) {
        S += part[(b * NSPLIT + ss) * EE + d];
    }

    const int xb  = b * LL;
    const int tL1 = __ldg(&xi[(xb + LL - 1) * stride]);
    const int tL2 = __ldg(&xi[(xb + LL - 2) * stride]);
    const int t0  = __ldg(&xi[(xb + 0) * stride]);
    const int t1  = __ldg(&xi[(xb + 1) * stride]);

    const float e0  = __ldg(&emb[0 * EE + d]);
    const float eL1 = __ldg(&emb[tL1 * EE + d]);
    const float eL2 = __ldg(&emb[tL2 * EE + d]);
    const float ef0 = __ldg(&emb[t0 * EE + d]);
    const float ef1 = __ldg(&emb[t1 * EE + d]);

    float* ob = out + b * 4 * EE;
    ob[0 * EE + d] = S - eL1 + e0;               // offset -1
    ob[1 * EE + d] = S - eL1 - eL2 + 2.0f * e0;  // offset -2
    ob[2 * EE + d] = S - ef0 + e0;               // offset +1
    ob[3 * EE + d] = S - ef0 - ef1 + 2.0f * e0;  // offset +2
}

// ---------------------------------------------------------------------------
extern "C" void kernel_launch(void* const* d_in, const int* in_sizes, int n_in,
                              void* d_out, int out_size) {
    const int*   xi  = (const int*)d_in[0];    // x: [64,2048] int64 or int32
    const float* emb = (const float*)d_in[1];  // emb: [100000,128] f32
    float*       out = (float*)d_out;          // [64,4,128] f32

    cbow_fused_kernel<<<dim3(BB, NSPLIT), 128>>>(xi, emb, out);
}